// round 1
// baseline (speedup 1.0000x reference)
#include <cuda_runtime.h>
#include <cstdint>

#define PP 32000
#define DD 128
#define BB 4096

// Scratch for hidden activations, [b][d] row-major. 2 MB.
__device__ float g_hidden[BB * DD];

// ---------------------------------------------------------------------------
// Kernel 1: hidden[b][d] = relu(sum_m W[d, x[b,m]])
// W is [D, P] row-major. Gather is inherently uncoalesced but touches at most
// ~4 MB of distinct W sectors -> L2-resident, a few microseconds.
// ---------------------------------------------------------------------------
__global__ void hidden_kernel(const int* __restrict__ x,
                              const float* __restrict__ W,
                              int M) {
    int b = blockIdx.x;
    int d = threadIdx.x;
    const int* xb = x + b * M;
    float acc = 0.0f;
    for (int m = 0; m < M; ++m) {
        int tok = xb[m];
        acc += W[(size_t)d * PP + tok];
    }
    g_hidden[b * DD + d] = fmaxf(acc, 0.0f);
}

// ---------------------------------------------------------------------------
// Kernel 2: out[b][p] = sum_d hidden[b][d] * V[p][d]
// 128(b) x 128(p) tile per block, 256 threads, 8x8 micro-tile per thread.
// Inner product uses packed fma.rn.f32x2 (FFMA2): accumulator pairs span two
// adjacent p-columns; the hidden value is duplicated into both 32-bit lanes.
// K = 128 split into KC = 32 chunks through shared memory.
// ---------------------------------------------------------------------------
#define TBB 128
#define TPP 128
#define KC  32

__global__ __launch_bounds__(256, 2)
void gemm_kernel(const float* __restrict__ Vm, float* __restrict__ out) {
    __shared__ float As[KC][TBB];  // [k][b]
    __shared__ float Bs[KC][TPP];  // [k][p]

    const int t  = threadIdx.x;
    const int tx = t & 15;   // p direction (8 cols each)
    const int ty = t >> 4;   // b direction (8 rows each)
    const int pBase = blockIdx.x * TPP;
    const int bBase = blockIdx.y * TBB;

    unsigned long long acc[8][4];
#pragma unroll
    for (int i = 0; i < 8; ++i)
#pragma unroll
        for (int j = 0; j < 4; ++j) acc[i][j] = 0ull;

    for (int kc = 0; kc < DD; kc += KC) {
        // --- Load A tile: 128 rows x 32 k of g_hidden, transposed into As ---
#pragma unroll
        for (int i = 0; i < 4; ++i) {
            int f   = t * 4 + i;        // 0..1023 float4 slots
            int row = f >> 3;           // 0..127
            int k4  = (f & 7) * 4;      // 0..28
            float4 v = *(const float4*)&g_hidden[(size_t)(bBase + row) * DD + kc + k4];
            As[k4 + 0][row] = v.x;
            As[k4 + 1][row] = v.y;
            As[k4 + 2][row] = v.z;
            As[k4 + 3][row] = v.w;
        }
        // --- Load B tile: 128 rows x 32 k of V, transposed into Bs ---
#pragma unroll
        for (int i = 0; i < 4; ++i) {
            int f   = t * 4 + i;
            int row = f >> 3;
            int k4  = (f & 7) * 4;
            float4 v = *(const float4*)&Vm[(size_t)(pBase + row) * DD + kc + k4];
            Bs[k4 + 0][row] = v.x;
            Bs[k4 + 1][row] = v.y;
            Bs[k4 + 2][row] = v.z;
            Bs[k4 + 3][row] = v.w;
        }
        __syncthreads();

#pragma unroll
        for (int kk = 0; kk < KC; ++kk) {
            float4 a0 = *(const float4*)&As[kk][ty * 8];
            float4 a1 = *(const float4*)&As[kk][ty * 8 + 4];
            ulonglong2 b0 = *(const ulonglong2*)&Bs[kk][tx * 8];
            ulonglong2 b1 = *(const ulonglong2*)&Bs[kk][tx * 8 + 4];

            float av[8] = {a0.x, a0.y, a0.z, a0.w, a1.x, a1.y, a1.z, a1.w};
            unsigned long long bv[4] = {b0.x, b0.y, b1.x, b1.y};

#pragma unroll
            for (int i = 0; i < 8; ++i) {
                unsigned int au = __float_as_uint(av[i]);
                unsigned long long a2;
                asm("mov.b64 %0, {%1, %2};" : "=l"(a2) : "r"(au), "r"(au));
#pragma unroll
                for (int j = 0; j < 4; ++j) {
                    asm("fma.rn.f32x2 %0, %1, %2, %0;"
                        : "+l"(acc[i][j])
                        : "l"(a2), "l"(bv[j]));
                }
            }
        }
        __syncthreads();
    }

    // --- Epilogue: unpack pairs and store 8x8 tile as 2x float4 per row ---
#pragma unroll
    for (int i = 0; i < 8; ++i) {
        float o[8];
#pragma unroll
        for (int j = 0; j < 4; ++j) {
            unsigned int lo, hi;
            asm("mov.b64 {%0, %1}, %2;" : "=r"(lo), "=r"(hi) : "l"(acc[i][j]));
            o[2 * j]     = __uint_as_float(lo);
            o[2 * j + 1] = __uint_as_float(hi);
        }
        size_t base = (size_t)(bBase + ty * 8 + i) * PP + pBase + tx * 8;
        *(float4*)&out[base]     = make_float4(o[0], o[1], o[2], o[3]);
        *(float4*)&out[base + 4] = make_float4(o[4], o[5], o[6], o[7]);
    }
}

// ---------------------------------------------------------------------------
extern "C" void kernel_launch(void* const* d_in, const int* in_sizes, int n_in,
                              void* d_out, int out_size) {
    const int*   x  = (const int*)d_in[0];    // [B, M] token indices
    const float* W  = (const float*)d_in[1];  // [D, P]
    const float* Vm = (const float*)d_in[2];  // [P, D]
    float* out = (float*)d_out;               // [B, P]

    int M = in_sizes[0] / BB;                 // = 2

    hidden_kernel<<<BB, DD>>>(x, W, M);

    dim3 grid(PP / TPP, BB / TBB);            // (250, 32)
    gemm_kernel<<<grid, 256>>>(Vm, out);
}

// round 3
// speedup vs baseline: 3.3230x; 3.3230x over previous
#include <cuda_runtime.h>
#include <cstdint>

#define PP 32000
#define DD 128
#define BB 4096

// tf32-rounded operands
__device__ float g_hidden[BB * DD];   // [b][d]
__device__ float g_Vt[PP * DD];       // [p][d]

__device__ __forceinline__ uint32_t smem_u32(const void* p) {
    uint32_t a;
    asm("{ .reg .u64 t; cvta.to.shared.u64 t, %1; cvt.u32.u64 %0, t; }" : "=r"(a) : "l"(p));
    return a;
}
__device__ __forceinline__ float tf32r(float x) {
    uint32_t t; asm("cvt.rna.tf32.f32 %0, %1;" : "=r"(t) : "f"(x));
    return __uint_as_float(t);
}

// ---------------------------------------------------------- prologue kernels
__global__ void hidden_kernel(const int* __restrict__ x, const float* __restrict__ W, int M) {
    int b = blockIdx.x;
    int d = threadIdx.x;
    const int* xb = x + b * M;
    float acc = 0.0f;
    for (int m = 0; m < M; ++m) acc += W[(size_t)d * PP + xb[m]];
    g_hidden[b * DD + d] = tf32r(fmaxf(acc, 0.0f));
}

__global__ void vconv_kernel(const float* __restrict__ V) {
    int i = blockIdx.x * blockDim.x + threadIdx.x;
    const float4* src = (const float4*)V;
    float4* dst = (float4*)g_Vt;
    int n4 = PP * DD / 4;
    for (; i < n4; i += gridDim.x * blockDim.x) {
        float4 v = src[i];
        v.x = tf32r(v.x); v.y = tf32r(v.y); v.z = tf32r(v.z); v.w = tf32r(v.w);
        dst[i] = v;
    }
}

// --------------------------------------------------------------- GEMM kernel
// out[b][p] = sum_d hidden[b][d] * V[p][d]
// CTA tile 128(b) x 128(p), K = 128 all in smem.
// 8 warps as 2(m) x 4(n); warp tile 64 x 32; mma.sync m16n8k8 tf32.
// A tile loaded once per block; B tiles double-buffered via cp.async.
#define TM 128
#define TN 128
#define NPT (PP / TN)   // 250
#define SPLIT 9
#define PCHUNK 28

#define SM_A  0
#define SM_B0 65536
#define SM_B1 131072
#define SMEM_TOTAL 196608

// row-major [row][128 f32] with 16B-chunk swizzle: chunk c -> c ^ (row & 7)
__device__ __forceinline__ void load_tile_async(uint32_t dstBase, const float* __restrict__ g, int tid) {
#pragma unroll
    for (int i = 0; i < 16; ++i) {
        int slot = tid + i * 256;      // 0..4095 float4 slots
        int row  = slot >> 5;          // 0..127
        int c    = slot & 31;          // chunk within row
        uint32_t dst = dstBase + row * 512 + (((uint32_t)(c ^ (row & 7))) << 4);
        const float* src = g + row * DD + c * 4;
        asm volatile("cp.async.cg.shared.global [%0], [%1], 16;" :: "r"(dst), "l"(src));
    }
}

__device__ __forceinline__ void ldsm_x4(uint32_t* r, uint32_t addr) {
    asm volatile("ldmatrix.sync.aligned.m8n8.x4.shared.b16 {%0,%1,%2,%3}, [%4];"
                 : "=r"(r[0]), "=r"(r[1]), "=r"(r[2]), "=r"(r[3]) : "r"(addr));
}

__device__ __forceinline__ void mma_tf32(float* c, const uint32_t* a, const uint32_t* b) {
    asm volatile(
        "mma.sync.aligned.m16n8k8.row.col.f32.tf32.tf32.f32 "
        "{%0,%1,%2,%3}, {%4,%5,%6,%7}, {%8,%9}, {%0,%1,%2,%3};"
        : "+f"(c[0]), "+f"(c[1]), "+f"(c[2]), "+f"(c[3])
        : "r"(a[0]), "r"(a[1]), "r"(a[2]), "r"(a[3]), "r"(b[0]), "r"(b[1]));
}

__global__ __launch_bounds__(256, 1)
void gemm_mma(float* __restrict__ out) {
    extern __shared__ char smem[];
    uint32_t sb = smem_u32(smem);
    const int tid = threadIdx.x;
    const int wid = tid >> 5;
    const int lane = tid & 31;
    const int warpM = wid >> 2;       // 0..1  (64 rows each)
    const int warpN = wid & 3;        // 0..3  (32 cols each)
    const int g = lane >> 2;          // fragment group row
    const int t = lane & 3;           // fragment group col

    const int bTile = blockIdx.y;
    const int p0 = blockIdx.x * PCHUNK;
    const int p1 = min(NPT, p0 + PCHUNK);
    const int nT = p1 - p0;

    // ---- per-thread ldmatrix address components ----
    // A fragment (m16k8): lanes 0-15 -> rows, lanes 16-31 -> +16B half
    const int aRow  = warpM * 64 + (lane & 15);
    const int aHalf = lane >> 4;
    const int l7    = lane & 7;
    const uint32_t aBase = sb + SM_A + aRow * 512;   // + mi*8192 + xor-term
    // B fragment pair (2 x n8k8): lanes 0-7 n0-7/lo, 8-15 n0-7/hi, 16-23 n8-15/lo, 24-31 n8-15/hi
    const int bRowL = warpN * 32 + ((lane >> 4) << 3) + l7;
    const int bHalf = (lane >> 3) & 1;
    const uint32_t bRowOff = bRowL * 512;            // + nj*8192 + xor-term

    // ---- prologue loads: A tile (persists) + first B tile ----
    load_tile_async(sb + SM_A, g_hidden + (size_t)bTile * TM * DD, tid);
    load_tile_async(sb + SM_B0, g_Vt + (size_t)p0 * TN * DD, tid);
    asm volatile("cp.async.commit_group;");
    asm volatile("cp.async.wait_group 0;" ::: "memory");
    __syncthreads();

    for (int it = 0; it < nT; ++it) {
        const uint32_t bbuf = sb + ((it & 1) ? SM_B1 : SM_B0);
        const uint32_t obuf = sb + ((it & 1) ? SM_B0 : SM_B1);

        if (it + 1 < nT) {
            load_tile_async(obuf, g_Vt + (size_t)(p0 + it + 1) * TN * DD, tid);
            asm volatile("cp.async.commit_group;");
        }

        float c[16][4];
#pragma unroll
        for (int i = 0; i < 16; ++i) { c[i][0] = 0.f; c[i][1] = 0.f; c[i][2] = 0.f; c[i][3] = 0.f; }

#pragma unroll
        for (int ks = 0; ks < 16; ++ks) {
            const uint32_t axor = ((uint32_t)((ks * 2 + aHalf) ^ l7)) << 4;
            const uint32_t bxor = ((uint32_t)((ks * 2 + bHalf) ^ l7)) << 4;

            uint32_t a[4][4];
#pragma unroll
            for (int mi = 0; mi < 4; ++mi)
                ldsm_x4(a[mi], aBase + mi * 8192 + axor);

            uint32_t b[2][4];
#pragma unroll
            for (int nj = 0; nj < 2; ++nj)
                ldsm_x4(b[nj], bbuf + bRowOff + nj * 8192 + bxor);

#pragma unroll
            for (int mi = 0; mi < 4; ++mi) {
#pragma unroll
                for (int ni = 0; ni < 4; ++ni)
                    mma_tf32(c[mi * 4 + ni], a[mi], &b[ni >> 1][(ni & 1) * 2]);
            }
        }

        // ---- epilogue: direct register -> gmem stores (float2, 8B) ----
        const size_t colBase = (size_t)(p0 + it) * TN + warpN * 32 + 2 * t;
#pragma unroll
        for (int mi = 0; mi < 4; ++mi) {
            const size_t row = (size_t)(bTile * TM + warpM * 64 + mi * 16 + g);
#pragma unroll
            for (int ni = 0; ni < 4; ++ni) {
                const float* cc = c[mi * 4 + ni];
                size_t col = colBase + ni * 8;
                *(float2*)&out[row * PP + col]       = make_float2(cc[0], cc[1]);
                *(float2*)&out[(row + 8) * PP + col] = make_float2(cc[2], cc[3]);
            }
        }

        if (it + 1 < nT)
            asm volatile("cp.async.wait_group 0;" ::: "memory");
        __syncthreads();
    }
}

// ---------------------------------------------------------------------------
extern "C" void kernel_launch(void* const* d_in, const int* in_sizes, int n_in,
                              void* d_out, int out_size) {
    const int*   x  = (const int*)d_in[0];    // [B, M]
    const float* W  = (const float*)d_in[1];  // [D, P]
    const float* Vm = (const float*)d_in[2];  // [P, D]
    float* out = (float*)d_out;               // [B, P]

    int M = in_sizes[0] / BB;                 // = 2

    hidden_kernel<<<BB, DD>>>(x, W, M);
    vconv_kernel<<<1024, 256>>>(Vm);

    cudaFuncSetAttribute(gemm_mma, cudaFuncAttributeMaxDynamicSharedMemorySize, SMEM_TOTAL);
    dim3 grid(SPLIT, BB / TM);                // (9, 32) = 288 blocks
    gemm_mma<<<grid, 256, SMEM_TOTAL>>>(out);
}

// round 4
// speedup vs baseline: 3.5021x; 1.0539x over previous
#include <cuda_runtime.h>
#include <cstdint>

#define PP 32000
#define DD 128
#define BB 4096

// tf32-rounded operands
__device__ float g_hidden[BB * DD];   // [b][d]
__device__ float g_Vt[PP * DD];       // [p][d]

__device__ __forceinline__ uint32_t smem_u32(const void* p) {
    uint32_t a;
    asm("{ .reg .u64 t; cvta.to.shared.u64 t, %1; cvt.u32.u64 %0, t; }" : "=r"(a) : "l"(p));
    return a;
}
__device__ __forceinline__ float tf32r(float x) {
    uint32_t t; asm("cvt.rna.tf32.f32 %0, %1;" : "=r"(t) : "f"(x));
    return __uint_as_float(t);
}

// ---------------------------------------------------------- prologue kernels
__global__ void hidden_kernel(const int* __restrict__ x, const float* __restrict__ W, int M) {
    int b = blockIdx.x;
    int d = threadIdx.x;
    const int* xb = x + b * M;
    float acc = 0.0f;
    for (int m = 0; m < M; ++m) acc += W[(size_t)d * PP + xb[m]];
    g_hidden[b * DD + d] = tf32r(fmaxf(acc, 0.0f));
}

__global__ void vconv_kernel(const float* __restrict__ V) {
    int i = blockIdx.x * blockDim.x + threadIdx.x;
    const float4* src = (const float4*)V;
    float4* dst = (float4*)g_Vt;
    int n4 = PP * DD / 4;
    for (; i < n4; i += gridDim.x * blockDim.x) {
        float4 v = src[i];
        v.x = tf32r(v.x); v.y = tf32r(v.y); v.z = tf32r(v.z); v.w = tf32r(v.w);
        dst[i] = v;
    }
}

// --------------------------------------------------------------- GEMM kernel
// out[b][p] = sum_d hidden[b][d] * V[p][d]
// CTA tile 256(b) x 128(p), K = 128. 512 threads, 16 warps as 4(m) x 4(n),
// warp tile 64 x 32, mma.sync m16n8k8 tf32.
// A (256x128 f32, 128KB) loaded once per CTA. B streamed as K-halves
// (128 rows x 64 f32 = 32KB) through a 3-buffer cp.async ring.
#define TMB 256
#define TN  128
#define NPT (PP / TN)   // 250
#define SPLIT 9
#define PCHUNK 28       // ceil(250/9)

#define SM_A   0
#define SM_B   131072           // 3 x 32768
#define SMEM_TOTAL 229376

__device__ __forceinline__ void load_A_async(uint32_t sb, const float* __restrict__ g, int tid) {
#pragma unroll
    for (int i = 0; i < 16; ++i) {
        int slot = tid + i * 512;      // 0..8191 float4 slots
        int row  = slot >> 5;          // 0..255
        int c    = slot & 31;
        uint32_t dst = sb + SM_A + row * 512 + (((uint32_t)(c ^ (row & 7))) << 4);
        const float* src = g + row * DD + c * 4;
        asm volatile("cp.async.cg.shared.global [%0], [%1], 16;" :: "r"(dst), "l"(src));
    }
}

// one K-half of a B tile: 128 rows x 64 f32, row stride 256B, 16B-chunk swizzle
__device__ __forceinline__ void load_Bhalf_async(uint32_t dstBase, const float* __restrict__ g,
                                                 int h, int tid) {
#pragma unroll
    for (int i = 0; i < 4; ++i) {
        int slot = tid + i * 512;      // 0..2047 float4 slots
        int row  = slot >> 4;          // 0..127
        int c    = slot & 15;
        uint32_t dst = dstBase + row * 256 + (((uint32_t)(c ^ (row & 7))) << 4);
        const float* src = g + row * DD + h * 64 + c * 4;
        asm volatile("cp.async.cg.shared.global [%0], [%1], 16;" :: "r"(dst), "l"(src));
    }
}

__device__ __forceinline__ void ldsm_x4(uint32_t* r, uint32_t addr) {
    asm volatile("ldmatrix.sync.aligned.m8n8.x4.shared.b16 {%0,%1,%2,%3}, [%4];"
                 : "=r"(r[0]), "=r"(r[1]), "=r"(r[2]), "=r"(r[3]) : "r"(addr));
}

__device__ __forceinline__ void mma_tf32(float* c, const uint32_t* a, const uint32_t* b) {
    asm volatile(
        "mma.sync.aligned.m16n8k8.row.col.f32.tf32.tf32.f32 "
        "{%0,%1,%2,%3}, {%4,%5,%6,%7}, {%8,%9}, {%0,%1,%2,%3};"
        : "+f"(c[0]), "+f"(c[1]), "+f"(c[2]), "+f"(c[3])
        : "r"(a[0]), "r"(a[1]), "r"(a[2]), "r"(a[3]), "r"(b[0]), "r"(b[1]));
}

__global__ __launch_bounds__(512, 1)
void gemm_mma(float* __restrict__ out) {
    extern __shared__ char smem[];
    uint32_t sb = smem_u32(smem);
    const int tid  = threadIdx.x;
    const int wid  = tid >> 5;
    const int lane = tid & 31;
    const int warpM = wid >> 2;       // 0..3  (64 rows each)
    const int warpN = wid & 3;        // 0..3  (32 cols each)
    const int g = lane >> 2;
    const int t = lane & 3;

    const int bTile = blockIdx.y;
    const int p0 = blockIdx.x * PCHUNK;
    const int p1 = min(NPT, p0 + PCHUNK);
    const int nT = p1 - p0;
    const int nS = 2 * nT;            // K-half steps

    // A fragment addressing (m16k8): lanes 0-15 rows, 16-31 +16B half
    const int aRow  = warpM * 64 + (lane & 15);
    const int aHalf = lane >> 4;
    const int l7    = lane & 7;
    const uint32_t aBase = sb + SM_A + aRow * 512;          // + mi*8192 + xor<<4
    // B fragment addressing (2 x n8k8 per ldsm.x4)
    const int bRowL = warpN * 32 + ((lane >> 4) << 3) + l7;
    const int bHalf = (lane >> 3) & 1;
    const uint32_t bRowOff = (uint32_t)bRowL * 256;         // + nj*4096 + xor<<4

    // ---- prologue: A (group 0) + first two B halves (groups 1, 2) ----
    load_A_async(sb, g_hidden + (size_t)bTile * TMB * DD, tid);
    asm volatile("cp.async.commit_group;");
    load_Bhalf_async(sb + SM_B, g_Vt + (size_t)p0 * TN * DD, 0, tid);
    asm volatile("cp.async.commit_group;");
    load_Bhalf_async(sb + SM_B + 32768, g_Vt + (size_t)p0 * TN * DD, 1, tid);
    asm volatile("cp.async.commit_group;");

    float c[16][4];

    for (int s = 0; s < nS; ++s) {
        // wait until K-half s is resident (keep later prefetches in flight)
        if (s + 1 < nS) asm volatile("cp.async.wait_group 1;" ::: "memory");
        else            asm volatile("cp.async.wait_group 0;" ::: "memory");
        __syncthreads();

        // prefetch K-half s+2 into ring slot (s+2)%3 (that buffer was consumed at s-1)
        if (s + 2 < nS) {
            int ns = s + 2;
            load_Bhalf_async(sb + SM_B + (ns % 3) * 32768,
                             g_Vt + (size_t)(p0 + (ns >> 1)) * TN * DD, ns & 1, tid);
            asm volatile("cp.async.commit_group;");
        }

        const int h = s & 1;
        const uint32_t bbuf = sb + SM_B + (s % 3) * 32768;

        if (h == 0) {
#pragma unroll
            for (int i = 0; i < 16; ++i) { c[i][0] = 0.f; c[i][1] = 0.f; c[i][2] = 0.f; c[i][3] = 0.f; }
        }

#pragma unroll
        for (int ks = 0; ks < 8; ++ks) {
            const uint32_t axor = ((uint32_t)(((h * 8 + ks) * 2 + aHalf) ^ l7)) << 4;
            const uint32_t bxor = ((uint32_t)((ks * 2 + bHalf) ^ l7)) << 4;

            uint32_t a[4][4];
#pragma unroll
            for (int mi = 0; mi < 4; ++mi)
                ldsm_x4(a[mi], aBase + mi * 8192 + axor);

            uint32_t b[2][4];
#pragma unroll
            for (int nj = 0; nj < 2; ++nj)
                ldsm_x4(b[nj], bbuf + bRowOff + nj * 4096 + bxor);

#pragma unroll
            for (int mi = 0; mi < 4; ++mi)
#pragma unroll
                for (int ni = 0; ni < 4; ++ni)
                    mma_tf32(c[mi * 4 + ni], a[mi], &b[ni >> 1][(ni & 1) * 2]);
        }

        if (h == 1) {
            // ---- epilogue: register -> gmem stores (float2) ----
            const int tile = s >> 1;
            const size_t colBase = (size_t)(p0 + tile) * TN + warpN * 32 + 2 * t;
#pragma unroll
            for (int mi = 0; mi < 4; ++mi) {
                const size_t row = (size_t)(bTile * TMB + warpM * 64 + mi * 16 + g);
#pragma unroll
                for (int ni = 0; ni < 4; ++ni) {
                    const float* cc = c[mi * 4 + ni];
                    size_t col = colBase + ni * 8;
                    *(float2*)&out[row * PP + col]       = make_float2(cc[0], cc[1]);
                    *(float2*)&out[(row + 8) * PP + col] = make_float2(cc[2], cc[3]);
                }
            }
        }
    }
}

// ---------------------------------------------------------------------------
extern "C" void kernel_launch(void* const* d_in, const int* in_sizes, int n_in,
                              void* d_out, int out_size) {
    const int*   x  = (const int*)d_in[0];    // [B, M]
    const float* W  = (const float*)d_in[1];  // [D, P]
    const float* Vm = (const float*)d_in[2];  // [P, D]
    float* out = (float*)d_out;               // [B, P]

    int M = in_sizes[0] / BB;                 // = 2

    hidden_kernel<<<BB, DD>>>(x, W, M);
    vconv_kernel<<<1024, 256>>>(Vm);

    cudaFuncSetAttribute(gemm_mma, cudaFuncAttributeMaxDynamicSharedMemorySize, SMEM_TOTAL);
    dim3 grid(SPLIT, BB / TMB);               // (9, 16) = 144 blocks = 1 wave
    gemm_mma<<<grid, 512, SMEM_TOTAL>>>(out);
}

// round 6
// speedup vs baseline: 3.5455x; 1.0124x over previous
#include <cuda_runtime.h>
#include <cstdint>

#define PP 32000
#define DD 128
#define BB 4096

// tf32-rounded operands
__device__ float g_hidden[BB * DD];   // [b][d]
__device__ float g_Vt[PP * DD];       // [p][d]

__device__ __forceinline__ uint32_t smem_u32(const void* p) {
    uint32_t a;
    asm("{ .reg .u64 t; cvta.to.shared.u64 t, %1; cvt.u32.u64 %0, t; }" : "=r"(a) : "l"(p));
    return a;
}
__device__ __forceinline__ float tf32r(float x) {
    uint32_t t; asm("cvt.rna.tf32.f32 %0, %1;" : "=r"(t) : "f"(x));
    return __uint_as_float(t);
}

// ------------------------------------------------- merged prologue kernel
// blocks [0, 4096): hidden[b][d] = tf32(relu(sum_m W[d, x[b,m]]))
// blocks [4096, 6144): g_Vt = tf32(V)
#define HID_BLOCKS 4096
#define VC_BLOCKS  2048
__global__ void prologue_kernel(const int* __restrict__ x, const float* __restrict__ W,
                                const float* __restrict__ V, int M) {
    if (blockIdx.x < HID_BLOCKS) {
        int b = blockIdx.x;
        int d = threadIdx.x;
        const int* xb = x + b * M;
        float acc = 0.0f;
        for (int m = 0; m < M; ++m) acc += W[(size_t)d * PP + xb[m]];
        g_hidden[b * DD + d] = tf32r(fmaxf(acc, 0.0f));
    } else {
        int i = (blockIdx.x - HID_BLOCKS) * blockDim.x + threadIdx.x;
        const float4* src = (const float4*)V;
        float4* dst = (float4*)g_Vt;
        const int n4 = PP * DD / 4;
        const int stride = VC_BLOCKS * blockDim.x;
        for (; i < n4; i += stride) {
            float4 v = src[i];
            v.x = tf32r(v.x); v.y = tf32r(v.y); v.z = tf32r(v.z); v.w = tf32r(v.w);
            dst[i] = v;
        }
    }
}

// --------------------------------------------------------------- GEMM kernel
// out[b][p] = sum_d hidden[b][d] * V[p][d]
// CTA tile 256(b) x 128(p), K = 128. 256 threads, 8 warps as 4(m) x 2(n),
// warp tile 64 x 64, mma.sync m16n8k8 tf32.
// A (256x128 f32, 128KB) loaded once per CTA. B streamed as K-halves
// (128 rows x 64 f32 = 32KB) through a 3-buffer cp.async ring.
#define TMB 256
#define TN  128
#define NPT (PP / TN)   // 250
#define SPLIT 9
#define PCHUNK 28       // ceil(250/9)

#define SM_A   0
#define SM_B   131072           // 3 x 32768
#define SMEM_TOTAL 229376

__device__ __forceinline__ void load_A_async(uint32_t sb, const float* __restrict__ g, int tid) {
#pragma unroll
    for (int i = 0; i < 32; ++i) {
        int slot = tid + i * 256;      // 0..8191 float4 slots
        int row  = slot >> 5;          // 0..255
        int c    = slot & 31;
        uint32_t dst = sb + SM_A + row * 512 + (((uint32_t)(c ^ (row & 7))) << 4);
        const float* src = g + row * DD + c * 4;
        asm volatile("cp.async.cg.shared.global [%0], [%1], 16;" :: "r"(dst), "l"(src));
    }
}

// one K-half of a B tile: 128 rows x 64 f32, row stride 256B, 16B-chunk swizzle
__device__ __forceinline__ void load_Bhalf_async(uint32_t dstBase, const float* __restrict__ g,
                                                 int h, int tid) {
#pragma unroll
    for (int i = 0; i < 8; ++i) {
        int slot = tid + i * 256;      // 0..2047 float4 slots
        int row  = slot >> 4;          // 0..127
        int c    = slot & 15;
        uint32_t dst = dstBase + row * 256 + (((uint32_t)(c ^ (row & 7))) << 4);
        const float* src = g + row * DD + h * 64 + c * 4;
        asm volatile("cp.async.cg.shared.global [%0], [%1], 16;" :: "r"(dst), "l"(src));
    }
}

__device__ __forceinline__ void ldsm_x4(uint32_t* r, uint32_t addr) {
    asm volatile("ldmatrix.sync.aligned.m8n8.x4.shared.b16 {%0,%1,%2,%3}, [%4];"
                 : "=r"(r[0]), "=r"(r[1]), "=r"(r[2]), "=r"(r[3]) : "r"(addr));
}

__device__ __forceinline__ void mma_tf32(float* c, const uint32_t* a, const uint32_t* b) {
    asm volatile(
        "mma.sync.aligned.m16n8k8.row.col.f32.tf32.tf32.f32 "
        "{%0,%1,%2,%3}, {%4,%5,%6,%7}, {%8,%9}, {%0,%1,%2,%3};"
        : "+f"(c[0]), "+f"(c[1]), "+f"(c[2]), "+f"(c[3])
        : "r"(a[0]), "r"(a[1]), "r"(a[2]), "r"(a[3]), "r"(b[0]), "r"(b[1]));
}

__global__ __launch_bounds__(256, 1)
void gemm_mma(float* __restrict__ out) {
    extern __shared__ char smem[];
    uint32_t sb = smem_u32(smem);
    const int tid  = threadIdx.x;
    const int wid  = tid >> 5;
    const int lane = tid & 31;
    const int warpM = wid >> 1;       // 0..3  (64 rows each)
    const int warpN = wid & 1;        // 0..1  (64 cols each)
    const int g = lane >> 2;
    const int t = lane & 3;

    const int bTile = blockIdx.y;
    const int p0 = blockIdx.x * PCHUNK;
    const int p1 = min(NPT, p0 + PCHUNK);
    const int nT = p1 - p0;
    const int nS = 2 * nT;            // K-half steps

    // A fragment addressing (m16k8): lanes 0-15 rows, 16-31 +16B half
    const int aRow  = warpM * 64 + (lane & 15);
    const int aHalf = lane >> 4;
    const int l7    = lane & 7;
    const uint32_t aBase = sb + SM_A + aRow * 512;          // + mi*8192 + xor<<4
    // B fragment addressing (2 x n8k8 per ldsm.x4)
    const int bRowL = warpN * 64 + ((lane >> 4) << 3) + l7;
    const int bHalf = (lane >> 3) & 1;
    const uint32_t bRowOff = (uint32_t)bRowL * 256;         // + nj*4096 + xor<<4

    // ---- prologue: A (group 0) + first two B halves (groups 1, 2) ----
    load_A_async(sb, g_hidden + (size_t)bTile * TMB * DD, tid);
    asm volatile("cp.async.commit_group;");
    load_Bhalf_async(sb + SM_B, g_Vt + (size_t)p0 * TN * DD, 0, tid);
    asm volatile("cp.async.commit_group;");
    load_Bhalf_async(sb + SM_B + 32768, g_Vt + (size_t)p0 * TN * DD, 1, tid);
    asm volatile("cp.async.commit_group;");

    float c[32][4];

    for (int s = 0; s < nS; ++s) {
        if (s + 1 < nS) asm volatile("cp.async.wait_group 1;" ::: "memory");
        else            asm volatile("cp.async.wait_group 0;" ::: "memory");
        __syncthreads();

        // prefetch K-half s+2 into ring slot (s+2)%3
        if (s + 2 < nS) {
            int ns = s + 2;
            load_Bhalf_async(sb + SM_B + (ns % 3) * 32768,
                             g_Vt + (size_t)(p0 + (ns >> 1)) * TN * DD, ns & 1, tid);
            asm volatile("cp.async.commit_group;");
        }

        const int h = s & 1;
        const uint32_t bbuf = sb + SM_B + (s % 3) * 32768;

        if (h == 0) {
#pragma unroll
            for (int i = 0; i < 32; ++i) { c[i][0] = 0.f; c[i][1] = 0.f; c[i][2] = 0.f; c[i][3] = 0.f; }
        }

#pragma unroll
        for (int ks = 0; ks < 8; ++ks) {
            const uint32_t axor = ((uint32_t)(((h * 8 + ks) * 2 + aHalf) ^ l7)) << 4;
            const uint32_t bxor = ((uint32_t)((ks * 2 + bHalf) ^ l7)) << 4;

            uint32_t a[4][4];
#pragma unroll
            for (int mi = 0; mi < 4; ++mi)
                ldsm_x4(a[mi], aBase + mi * 8192 + axor);

            uint32_t b[4][4];
#pragma unroll
            for (int nj = 0; nj < 4; ++nj)
                ldsm_x4(b[nj], bbuf + bRowOff + nj * 4096 + bxor);

#pragma unroll
            for (int mi = 0; mi < 4; ++mi)
#pragma unroll
                for (int ni = 0; ni < 8; ++ni)
                    mma_tf32(c[mi * 8 + ni], a[mi], &b[ni >> 1][(ni & 1) * 2]);
        }

        if (h == 1) {
            // ---- epilogue: register -> gmem stores (float2) ----
            const int tile = s >> 1;
            const size_t colBase = (size_t)(p0 + tile) * TN + warpN * 64 + 2 * t;
#pragma unroll
            for (int mi = 0; mi < 4; ++mi) {
                const size_t row = (size_t)(bTile * TMB + warpM * 64 + mi * 16 + g);
#pragma unroll
                for (int ni = 0; ni < 8; ++ni) {
                    const float* cc = c[mi * 8 + ni];
                    size_t col = colBase + ni * 8;
                    *(float2*)&out[row * PP + col]       = make_float2(cc[0], cc[1]);
                    *(float2*)&out[(row + 8) * PP + col] = make_float2(cc[2], cc[3]);
                }
            }
        }
    }
}

// ---------------------------------------------------------------------------
extern "C" void kernel_launch(void* const* d_in, const int* in_sizes, int n_in,
                              void* d_out, int out_size) {
    const int*   x  = (const int*)d_in[0];    // [B, M]
    const float* W  = (const float*)d_in[1];  // [D, P]
    const float* Vm = (const float*)d_in[2];  // [P, D]
    float* out = (float*)d_out;               // [B, P]

    int M = in_sizes[0] / BB;                 // = 2

    prologue_kernel<<<HID_BLOCKS + VC_BLOCKS, DD>>>(x, W, Vm, M);

    cudaFuncSetAttribute(gemm_mma, cudaFuncAttributeMaxDynamicSharedMemorySize, SMEM_TOTAL);
    dim3 grid(SPLIT, BB / TMB);               // (9, 16) = 144 blocks = 1 wave
    gemm_mma<<<grid, 256, SMEM_TOTAL>>>(out);
}

// round 7
// speedup vs baseline: 3.5773x; 1.0090x over previous
#include <cuda_runtime.h>
#include <cstdint>

#define PP 32000
#define DD 128
#define BB 4096

// tf32-rounded operands
__device__ float g_hidden[BB * DD];   // [b][d]
__device__ float g_Vt[PP * DD];       // [p][d]

__device__ __forceinline__ uint32_t smem_u32(const void* p) {
    uint32_t a;
    asm("{ .reg .u64 t; cvta.to.shared.u64 t, %1; cvt.u32.u64 %0, t; }" : "=r"(a) : "l"(p));
    return a;
}
__device__ __forceinline__ float tf32r(float x) {
    uint32_t t; asm("cvt.rna.tf32.f32 %0, %1;" : "=r"(t) : "f"(x));
    return __uint_as_float(t);
}

// ------------------------------------------------- merged prologue kernel
#define HID_BLOCKS 4096
#define VC_BLOCKS  2048
__global__ void prologue_kernel(const int* __restrict__ x, const float* __restrict__ W,
                                const float* __restrict__ V, int M) {
    if (blockIdx.x < HID_BLOCKS) {
        int b = blockIdx.x;
        int d = threadIdx.x;
        const int* xb = x + b * M;
        float acc = 0.0f;
        for (int m = 0; m < M; ++m) acc += W[(size_t)d * PP + xb[m]];
        g_hidden[b * DD + d] = tf32r(fmaxf(acc, 0.0f));
    } else {
        int i = (blockIdx.x - HID_BLOCKS) * blockDim.x + threadIdx.x;
        const float4* src = (const float4*)V;
        float4* dst = (float4*)g_Vt;
        const int n4 = PP * DD / 4;
        const int stride = VC_BLOCKS * blockDim.x;
        for (; i < n4; i += stride) {
            float4 v = src[i];
            v.x = tf32r(v.x); v.y = tf32r(v.y); v.z = tf32r(v.z); v.w = tf32r(v.w);
            dst[i] = v;
        }
    }
}

// --------------------------------------------------------------- GEMM kernel
// out[b][p] = sum_d hidden[b][d] * V[p][d]
// CTA tile 128(b) x 128(p), K = 128. 128 threads, 4 warps as 2(m) x 2(n),
// warp tile 64 x 64, mma.sync m16n8k8 tf32. 2 CTAs/SM -> 16 warps/SM.
// A (128x128 f32, 64KB) loaded once per CTA. B streamed as K-quarters
// (128 rows x 32 f32 = 16KB) through a 3-slot cp.async ring (48KB).
#define TMB 128
#define TN  128
#define NPT (PP / TN)   // 250
#define SPLIT 9
#define PCHUNK 28       // ceil(250/9)

#define SM_A   0
#define SM_B   65536            // 3 x 16384
#define SMEM_TOTAL 114688      // 112 KB -> 2 CTAs/SM

// A tile: 128 rows x 512B, 16B-chunk swizzle within row (chunk ^ (row&7))
__device__ __forceinline__ void load_A_async(uint32_t sb, const float* __restrict__ g, int tid) {
#pragma unroll
    for (int i = 0; i < 32; ++i) {
        int slot = tid + i * 128;      // 0..4095 float4 slots
        int row  = slot >> 5;          // 0..127
        int c    = slot & 31;
        uint32_t dst = sb + SM_A + row * 512 + (((uint32_t)(c ^ (row & 7))) << 4);
        const float* src = g + row * DD + c * 4;
        asm volatile("cp.async.cg.shared.global [%0], [%1], 16;" :: "r"(dst), "l"(src));
    }
}

// one K-quarter of a B tile: 128 rows x 32 f32, row stride 128B (8 chunks)
__device__ __forceinline__ void load_Bq_async(uint32_t dstBase, const float* __restrict__ g,
                                              int q, int tid) {
#pragma unroll
    for (int i = 0; i < 8; ++i) {
        int slot = tid + i * 128;      // 0..1023 float4 slots
        int row  = slot >> 3;          // 0..127
        int c    = slot & 7;
        uint32_t dst = dstBase + row * 128 + (((uint32_t)(c ^ (row & 7))) << 4);
        const float* src = g + row * DD + q * 32 + c * 4;
        asm volatile("cp.async.cg.shared.global [%0], [%1], 16;" :: "r"(dst), "l"(src));
    }
}

__device__ __forceinline__ void ldsm_x4(uint32_t* r, uint32_t addr) {
    asm volatile("ldmatrix.sync.aligned.m8n8.x4.shared.b16 {%0,%1,%2,%3}, [%4];"
                 : "=r"(r[0]), "=r"(r[1]), "=r"(r[2]), "=r"(r[3]) : "r"(addr));
}

__device__ __forceinline__ void mma_tf32(float* c, const uint32_t* a, const uint32_t* b) {
    asm volatile(
        "mma.sync.aligned.m16n8k8.row.col.f32.tf32.tf32.f32 "
        "{%0,%1,%2,%3}, {%4,%5,%6,%7}, {%8,%9}, {%0,%1,%2,%3};"
        : "+f"(c[0]), "+f"(c[1]), "+f"(c[2]), "+f"(c[3])
        : "r"(a[0]), "r"(a[1]), "r"(a[2]), "r"(a[3]), "r"(b[0]), "r"(b[1]));
}

__global__ __launch_bounds__(128, 2)
void gemm_mma(float* __restrict__ out) {
    extern __shared__ char smem[];
    uint32_t sb = smem_u32(smem);
    const int tid  = threadIdx.x;
    const int wid  = tid >> 5;
    const int lane = tid & 31;
    const int warpM = wid >> 1;       // 0..1  (64 rows each)
    const int warpN = wid & 1;        // 0..1  (64 cols each)
    const int g = lane >> 2;
    const int t = lane & 3;

    const int bTile = blockIdx.y;
    const int p0 = blockIdx.x * PCHUNK;
    const int p1 = min(NPT, p0 + PCHUNK);
    const int nT = p1 - p0;
    const int nS = 4 * nT;            // K-quarter steps

    // A fragment addressing (m16k8): lanes 0-15 rows, 16-31 +16B half
    const int aRow  = warpM * 64 + (lane & 15);
    const int aHalf = lane >> 4;
    const int l7    = lane & 7;
    const uint32_t aBase = sb + SM_A + aRow * 512;          // + mi*8192 + chunk<<4
    // B fragment addressing (2 x n8k8 per ldsm.x4)
    const int bRowL = warpN * 64 + ((lane >> 4) << 3) + l7;
    const int bHalf = (lane >> 3) & 1;
    const uint32_t bRowOff = (uint32_t)bRowL * 128;         // + nj*2048 + chunk<<4

    // ---- prologue: A (group 0) + first two B quarters (groups 1, 2) ----
    load_A_async(sb, g_hidden + (size_t)bTile * TMB * DD, tid);
    asm volatile("cp.async.commit_group;");
    load_Bq_async(sb + SM_B, g_Vt + (size_t)p0 * TN * DD, 0, tid);
    asm volatile("cp.async.commit_group;");
    load_Bq_async(sb + SM_B + 16384, g_Vt + (size_t)p0 * TN * DD, 1, tid);
    asm volatile("cp.async.commit_group;");

    float c[32][4];

    for (int s = 0; s < nS; ++s) {
        if (s + 1 < nS) asm volatile("cp.async.wait_group 1;" ::: "memory");
        else            asm volatile("cp.async.wait_group 0;" ::: "memory");
        __syncthreads();

        // prefetch K-quarter s+2 into ring slot (s+2)%3
        if (s + 2 < nS) {
            int ns = s + 2;
            load_Bq_async(sb + SM_B + (ns % 3) * 16384,
                          g_Vt + (size_t)(p0 + (ns >> 2)) * TN * DD, ns & 3, tid);
            asm volatile("cp.async.commit_group;");
        }

        const int q = s & 3;
        const uint32_t bbuf = sb + SM_B + (s % 3) * 16384;

        if (q == 0) {
#pragma unroll
            for (int i = 0; i < 32; ++i) { c[i][0] = 0.f; c[i][1] = 0.f; c[i][2] = 0.f; c[i][3] = 0.f; }
        }

#pragma unroll
        for (int ks = 0; ks < 4; ++ks) {
            const int kk = q * 4 + ks;   // global k-step 0..15
            const uint32_t axor = ((uint32_t)((kk * 2 + aHalf) ^ l7)) << 4;
            const uint32_t bxor = ((uint32_t)((ks * 2 + bHalf) ^ l7)) << 4;

            uint32_t a[4][4];
#pragma unroll
            for (int mi = 0; mi < 4; ++mi)
                ldsm_x4(a[mi], aBase + mi * 8192 + axor);

            uint32_t b[4][4];
#pragma unroll
            for (int nj = 0; nj < 4; ++nj)
                ldsm_x4(b[nj], bbuf + bRowOff + nj * 2048 + bxor);

#pragma unroll
            for (int mi = 0; mi < 4; ++mi)
#pragma unroll
                for (int ni = 0; ni < 8; ++ni)
                    mma_tf32(c[mi * 8 + ni], a[mi], &b[ni >> 1][(ni & 1) * 2]);
        }

        if (q == 3) {
            // ---- epilogue: register -> gmem stores (float2) ----
            const int tile = s >> 2;
            const size_t colBase = (size_t)(p0 + tile) * TN + warpN * 64 + 2 * t;
#pragma unroll
            for (int mi = 0; mi < 4; ++mi) {
                const size_t row = (size_t)(bTile * TMB + warpM * 64 + mi * 16 + g);
#pragma unroll
                for (int ni = 0; ni < 8; ++ni) {
                    const float* cc = c[mi * 8 + ni];
                    size_t col = colBase + ni * 8;
                    *(float2*)&out[row * PP + col]       = make_float2(cc[0], cc[1]);
                    *(float2*)&out[(row + 8) * PP + col] = make_float2(cc[2], cc[3]);
                }
            }
        }
    }
}

// ---------------------------------------------------------------------------
extern "C" void kernel_launch(void* const* d_in, const int* in_sizes, int n_in,
                              void* d_out, int out_size) {
    const int*   x  = (const int*)d_in[0];    // [B, M]
    const float* W  = (const float*)d_in[1];  // [D, P]
    const float* Vm = (const float*)d_in[2];  // [P, D]
    float* out = (float*)d_out;               // [B, P]

    int M = in_sizes[0] / BB;                 // = 2

    prologue_kernel<<<HID_BLOCKS + VC_BLOCKS, DD>>>(x, W, Vm, M);

    cudaFuncSetAttribute(gemm_mma, cudaFuncAttributeMaxDynamicSharedMemorySize, SMEM_TOTAL);
    dim3 grid(SPLIT, BB / TMB);               // (9, 32) = 288 blocks, 2 CTAs/SM -> 1 wave
    gemm_mma<<<grid, 128, SMEM_TOTAL>>>(out);
}

// round 9
// speedup vs baseline: 5.3187x; 1.4868x over previous
#include <cuda_runtime.h>
#include <cuda_fp16.h>
#include <cstdint>

#define PP 32000
#define DD 128
#define BB 4096

// fp16 operands
__device__ __half g_hidden[BB * DD];   // [b][d]
__device__ __half g_Vt[PP * DD];       // [p][d]

__device__ __forceinline__ uint32_t smem_u32(const void* p) {
    uint32_t a;
    asm("{ .reg .u64 t; cvta.to.shared.u64 t, %1; cvt.u32.u64 %0, t; }" : "=r"(a) : "l"(p));
    return a;
}

// ------------------------------------------------- merged prologue kernel
#define HID_BLOCKS 4096
#define VC_BLOCKS  2048
__global__ void prologue_kernel(const int* __restrict__ x, const float* __restrict__ W,
                                const float* __restrict__ V, int M) {
    if (blockIdx.x < HID_BLOCKS) {
        int b = blockIdx.x;
        int d = threadIdx.x;
        const int* xb = x + b * M;
        float acc = 0.0f;
        for (int m = 0; m < M; ++m) acc += W[(size_t)d * PP + xb[m]];
        g_hidden[b * DD + d] = __float2half_rn(fmaxf(acc, 0.0f));
    } else {
        int i = (blockIdx.x - HID_BLOCKS) * blockDim.x + threadIdx.x;
        const float4* src = (const float4*)V;
        uint2* dst = (uint2*)g_Vt;
        const int n4 = PP * DD / 4;
        const int stride = VC_BLOCKS * blockDim.x;
        for (; i < n4; i += stride) {
            float4 v = src[i];
            __half2 lo = __floats2half2_rn(v.x, v.y);
            __half2 hi = __floats2half2_rn(v.z, v.w);
            dst[i] = make_uint2(*(uint32_t*)&lo, *(uint32_t*)&hi);
        }
    }
}

// --------------------------------------------------------------- GEMM kernel
// out[b][p] = sum_d hidden[b][d] * V[p][d], fp16 inputs, f32 accum.
// CTA tile 128(b) x 128(p), K = 128. 128 threads, 4 warps as 2(m) x 2(n),
// warp tile 64 x 64, mma.sync m16n8k16. 2 CTAs/SM.
// A (128x128 f16, 32KB) loaded once per CTA; B tiles (32KB) double-buffered.
#define TMB 128
#define TN  128
#define NPT (PP / TN)   // 250
#define SPLIT 9
#define PCHUNK 28       // ceil(250/9)

#define SM_A  0
#define SM_B  32768             // 2 x 32768
#define SMEM_TOTAL 98304       // 96 KB -> 2 CTAs/SM

// tile: 128 rows x 256B (128 f16); 16B chunks, swizzle chunk ^= (row & 7)
__device__ __forceinline__ void load_tile_async(uint32_t dstBase, const __half* __restrict__ g,
                                                int tid) {
#pragma unroll
    for (int i = 0; i < 16; ++i) {
        int slot = tid + i * 128;      // 0..2047 16B chunks
        int row  = slot >> 4;          // 0..127
        int c    = slot & 15;
        uint32_t dst = dstBase + row * 256 + (((uint32_t)(c ^ (row & 7))) << 4);
        const __half* src = g + row * DD + c * 8;
        asm volatile("cp.async.cg.shared.global [%0], [%1], 16;" :: "r"(dst), "l"(src));
    }
}

__device__ __forceinline__ void ldsm_x4(uint32_t* r, uint32_t addr) {
    asm volatile("ldmatrix.sync.aligned.m8n8.x4.shared.b16 {%0,%1,%2,%3}, [%4];"
                 : "=r"(r[0]), "=r"(r[1]), "=r"(r[2]), "=r"(r[3]) : "r"(addr));
}

__device__ __forceinline__ void mma_f16(float* c, const uint32_t* a, const uint32_t* b) {
    asm volatile(
        "mma.sync.aligned.m16n8k16.row.col.f32.f16.f16.f32 "
        "{%0,%1,%2,%3}, {%4,%5,%6,%7}, {%8,%9}, {%0,%1,%2,%3};"
        : "+f"(c[0]), "+f"(c[1]), "+f"(c[2]), "+f"(c[3])
        : "r"(a[0]), "r"(a[1]), "r"(a[2]), "r"(a[3]), "r"(b[0]), "r"(b[1]));
}

__global__ __launch_bounds__(128, 2)
void gemm_mma(float* __restrict__ out) {
    extern __shared__ char smem[];
    uint32_t sb = smem_u32(smem);
    const int tid  = threadIdx.x;
    const int wid  = tid >> 5;
    const int lane = tid & 31;
    const int warpM = wid >> 1;       // 0..1  (64 rows each)
    const int warpN = wid & 1;        // 0..1  (64 cols each)
    const int g = lane >> 2;
    const int t = lane & 3;

    const int bTile = blockIdx.y;
    const int p0 = blockIdx.x * PCHUNK;
    const int p1 = min(NPT, p0 + PCHUNK);
    const int nT = p1 - p0;

    // A fragment addressing (m16k16 via ldsm.x4 on b16 8x8s):
    // lanes 0-7: rows 0-7 khalf0; 8-15: rows 8-15 kh0; 16-23: rows 0-7 kh1; 24-31: rows 8-15 kh1
    const int aRow  = warpM * 64 + (lane & 15);
    const int aHalf = lane >> 4;                 // 16B k-half within k16 block
    const uint32_t aBase = sb + SM_A + aRow * 256;   // + mi*4096 + swchunk<<4
    const int aR7 = aRow & 7;
    // B fragment addressing (n16k16 per ldsm.x4):
    // lanes 0-15 -> rows n0-7 (kh = (lane>>3)&1), 16-31 -> rows n8-15
    const int bRow  = warpN * 64 + ((lane >> 4) << 3) + (lane & 7);
    const int bHalf = (lane >> 3) & 1;
    const uint32_t bRowOff = (uint32_t)bRow * 256;   // + nj*4096 + swchunk<<4
    const int bR7 = bRow & 7;

    // ---- prologue: A (group 0) + first B tile (group 1) ----
    load_tile_async(sb + SM_A, g_hidden + (size_t)bTile * TMB * DD, tid);
    asm volatile("cp.async.commit_group;");
    load_tile_async(sb + SM_B, g_Vt + (size_t)p0 * TN * DD, tid);
    asm volatile("cp.async.commit_group;");

    float c[32][4];

    for (int it = 0; it < nT; ++it) {
        // prefetch next B into the other buffer (safe: other buf not being read)
        if (it + 1 < nT) {
            load_tile_async(sb + SM_B + ((it + 1) & 1) * 32768,
                            g_Vt + (size_t)(p0 + it + 1) * TN * DD, tid);
            asm volatile("cp.async.commit_group;");
        }
        // wait until B_it (and A) resident; the just-issued prefetch may stay in flight
        if (it + 1 < nT) asm volatile("cp.async.wait_group 1;" ::: "memory");
        else             asm volatile("cp.async.wait_group 0;" ::: "memory");
        __syncthreads();

        const uint32_t bbuf = sb + SM_B + (it & 1) * 32768;

#pragma unroll
        for (int i = 0; i < 32; ++i) { c[i][0] = 0.f; c[i][1] = 0.f; c[i][2] = 0.f; c[i][3] = 0.f; }

#pragma unroll
        for (int ks = 0; ks < 8; ++ks) {           // k16 steps
            const uint32_t axor = ((uint32_t)((ks * 2 + aHalf) ^ aR7)) << 4;
            const uint32_t bxor = ((uint32_t)((ks * 2 + bHalf) ^ bR7)) << 4;

            uint32_t a[4][4];
#pragma unroll
            for (int mi = 0; mi < 4; ++mi)
                ldsm_x4(a[mi], aBase + mi * 4096 + axor);

            uint32_t b[4][4];
#pragma unroll
            for (int nj = 0; nj < 4; ++nj)
                ldsm_x4(b[nj], bbuf + bRowOff + nj * 4096 + bxor);

            // b[nj]: {r0,r1} = n(first 8) k-lo/k-hi, {r2,r3} = n(second 8)
#pragma unroll
            for (int mi = 0; mi < 4; ++mi)
#pragma unroll
                for (int ni = 0; ni < 8; ++ni)
                    mma_f16(c[mi * 8 + ni], a[mi], &b[ni >> 1][(ni & 1) * 2]);
        }

        // ---- epilogue: register -> gmem stores (float2) ----
        const size_t colBase = (size_t)(p0 + it) * TN + warpN * 64 + 2 * t;
#pragma unroll
        for (int mi = 0; mi < 4; ++mi) {
            const size_t row = (size_t)(bTile * TMB + warpM * 64 + mi * 16 + g);
#pragma unroll
            for (int ni = 0; ni < 8; ++ni) {
                const float* cc = c[mi * 8 + ni];
                size_t col = colBase + ni * 8;
                *(float2*)&out[row * PP + col]       = make_float2(cc[0], cc[1]);
                *(float2*)&out[(row + 8) * PP + col] = make_float2(cc[2], cc[3]);
            }
        }

        // protect the buffer the next iteration's prefetch will overwrite
        if (it + 1 < nT) __syncthreads();
    }
}

// ---------------------------------------------------------------------------
extern "C" void kernel_launch(void* const* d_in, const int* in_sizes, int n_in,
                              void* d_out, int out_size) {
    const int*   x  = (const int*)d_in[0];    // [B, M]
    const float* W  = (const float*)d_in[1];  // [D, P]
    const float* Vm = (const float*)d_in[2];  // [P, D]
    float* out = (float*)d_out;               // [B, P]

    int M = in_sizes[0] / BB;                 // = 2

    prologue_kernel<<<HID_BLOCKS + VC_BLOCKS, DD>>>(x, W, Vm, M);

    cudaFuncSetAttribute(gemm_mma, cudaFuncAttributeMaxDynamicSharedMemorySize, SMEM_TOTAL);
    dim3 grid(SPLIT, BB / TMB);               // (9, 32) = 288 blocks, 2 CTAs/SM
    gemm_mma<<<grid, 128, SMEM_TOTAL>>>(out);
}